// round 2
// baseline (speedup 1.0000x reference)
#include <cuda_runtime.h>

#define BATCH 2048
#define NCLS  1000
#define FDIM  128
#define TILE  64

// scratch (no allocations allowed)
__device__ float g_fnorm[BATCH];
__device__ float g_cnorm[1024];   // padded past 1000; garbage entries never stored

// One warp per row: squared L2 norm of feat rows (0..B-1) and center rows (B..B+C-1).
// Also zeroes the likelihood output slot (atomic accumulator target).
__global__ void norms_kernel(const float* __restrict__ feat,
                             const float* __restrict__ centers,
                             float* __restrict__ like_slot) {
    if (blockIdx.x == 0 && threadIdx.x == 0) *like_slot = 0.0f;
    int warp = (blockIdx.x * blockDim.x + threadIdx.x) >> 5;
    int lane = threadIdx.x & 31;
    if (warp >= BATCH + NCLS) return;
    const float* src = (warp < BATCH) ? (feat + (size_t)warp * FDIM)
                                      : (centers + (size_t)(warp - BATCH) * FDIM);
    float4 v = ((const float4*)src)[lane];           // 32 lanes x 4 = 128 elems
    float s = v.x * v.x + v.y * v.y + v.z * v.z + v.w * v.w;
    #pragma unroll
    for (int o = 16; o; o >>= 1) s += __shfl_xor_sync(0xffffffffu, s, o);
    if (lane == 0) {
        if (warp < BATCH) g_fnorm[warp] = s;
        else              g_cnorm[warp - BATCH] = s;
    }
}

// 64x64 output tile per block, 256 threads, 4x4 register blocking, full K=128 in smem.
__global__ __launch_bounds__(256) void lgm_kernel(
    const float* __restrict__ feat,
    const int* __restrict__ label,           // int32 (JAX default, x64 disabled)
    const float* __restrict__ centers,
    float* __restrict__ out)
{
    __shared__ float As[FDIM][TILE];   // k-major: As[k][row]
    __shared__ float Bs[FDIM][TILE];   // k-major: Bs[k][col]

    const int tid = threadIdx.x;
    const int rowBase = blockIdx.y * TILE;
    const int colBase = blockIdx.x * TILE;

    // Cooperative load + transpose. i = (kq, r): kq in [0,32), r in [0,64).
    // Threads in a group of 64 share kq, consecutive r -> conflict-free stores.
    for (int i = tid; i < TILE * (FDIM / 4); i += 256) {
        int kq = i >> 6, r = i & (TILE - 1);
        float4 a = ((const float4*)(feat + (size_t)(rowBase + r) * FDIM))[kq];
        As[4 * kq + 0][r] = a.x; As[4 * kq + 1][r] = a.y;
        As[4 * kq + 2][r] = a.z; As[4 * kq + 3][r] = a.w;
        int c = colBase + r;
        float4 b = make_float4(0.f, 0.f, 0.f, 0.f);
        if (c < NCLS) b = ((const float4*)(centers + (size_t)c * FDIM))[kq];
        Bs[4 * kq + 0][r] = b.x; Bs[4 * kq + 1][r] = b.y;
        Bs[4 * kq + 2][r] = b.z; Bs[4 * kq + 3][r] = b.w;
    }
    __syncthreads();

    const int tx = tid & 15;   // 16 col groups of 4
    const int ty = tid >> 4;   // 16 row groups of 4

    float acc[4][4] = {};
    #pragma unroll 8
    for (int k = 0; k < FDIM; k++) {
        float4 a = *(const float4*)&As[k][4 * ty];
        float4 b = *(const float4*)&Bs[k][4 * tx];
        float av[4] = {a.x, a.y, a.z, a.w};
        float bv[4] = {b.x, b.y, b.z, b.w};
        #pragma unroll
        for (int i = 0; i < 4; i++)
            #pragma unroll
            for (int j = 0; j < 4; j++)
                acc[i][j] += av[i] * bv[j];
    }

    float* logits = out;
    float* margin = out + (size_t)BATCH * NCLS;
    float* like   = out + 2ull * BATCH * NCLS;

    const int c0 = colBase + 4 * tx;
    if (c0 >= NCLS) return;   // 1000 % 4 == 0: vectors are all-or-nothing in bounds

    #pragma unroll
    for (int i = 0; i < 4; i++) {
        int b = rowBase + 4 * ty + i;
        float fn = g_fnorm[b];
        int lb = label[b];
        float lg[4], mg[4];
        #pragma unroll
        for (int j = 0; j < 4; j++) {
            int c = c0 + j;
            float dist = fn + g_cnorm[c] - 2.0f * acc[i][j];
            float l = -0.5f * dist;
            lg[j] = l;
            bool hit = (c == lb);
            mg[j] = hit ? 2.0f * l : l;
            if (hit) atomicAdd(like, 0.5f * dist * (1.0f / (float)BATCH));
        }
        *(float4*)(logits + (size_t)b * NCLS + c0) = make_float4(lg[0], lg[1], lg[2], lg[3]);
        *(float4*)(margin + (size_t)b * NCLS + c0) = make_float4(mg[0], mg[1], mg[2], mg[3]);
    }
}

extern "C" void kernel_launch(void* const* d_in, const int* in_sizes, int n_in,
                              void* d_out, int out_size) {
    const float* feat    = (const float*)d_in[0];
    const int*   label   = (const int*)d_in[1];
    const float* centers = (const float*)d_in[2];
    float*       out     = (float*)d_out;

    float* like_slot = out + 2ull * BATCH * NCLS;

    int warps = BATCH + NCLS;
    int nthreads = warps * 32;
    norms_kernel<<<(nthreads + 255) / 256, 256>>>(feat, centers, like_slot);

    dim3 grid((NCLS + TILE - 1) / TILE, BATCH / TILE);   // 16 x 32
    lgm_kernel<<<grid, 256>>>(feat, label, centers, out);
}

// round 4
// speedup vs baseline: 2.5714x; 2.5714x over previous
#include <cuda_runtime.h>
#include <cuda_bf16.h>
#include <cstdint>

#define BATCH 2048
#define NCLS  1000
#define FDIM  128
#define TM    128
#define TN    128

__device__ __forceinline__ uint32_t smem_u32(const void* p) {
    uint32_t a;
    asm("{ .reg .u64 t; cvta.to.shared.u64 t, %1; cvt.u32.u64 %0, t; }" : "=r"(a) : "l"(p));
    return a;
}

__device__ __forceinline__ uint32_t pack_bf16(float x, float y) {
    __nv_bfloat162 p = __float22bfloat162_rn(make_float2(x, y));
    return *(uint32_t*)&p;
}

#define LDSM_X4(r0, r1, r2, r3, addr) \
    asm volatile("ldmatrix.sync.aligned.m8n8.x4.shared.b16 {%0,%1,%2,%3}, [%4];" \
                 : "=r"(r0), "=r"(r1), "=r"(r2), "=r"(r3) : "r"(addr))

#define MMA_BF16(c, a, b) \
    asm volatile("mma.sync.aligned.m16n8k16.row.col.f32.bf16.bf16.f32 " \
                 "{%0,%1,%2,%3}, {%4,%5,%6,%7}, {%8,%9}, {%0,%1,%2,%3};" \
                 : "+f"((c)[0]), "+f"((c)[1]), "+f"((c)[2]), "+f"((c)[3]) \
                 : "r"((a)[0]), "r"((a)[1]), "r"((a)[2]), "r"((a)[3]), \
                   "r"((b)[0]), "r"((b)[1]))

__global__ void zero_like_kernel(float* like_slot) { *like_slot = 0.0f; }

// One fused kernel: tile fill (f32->bf16 convert + fp32 norms), HMMA GEMM, fused epilogue.
__global__ __launch_bounds__(256) void lgm_kernel(
    const float* __restrict__ feat,
    const int* __restrict__ label,
    const float* __restrict__ centers,
    float* __restrict__ out)
{
    // swizzled tiles: row stride 256B (128 bf16), chunk = 16B, chunk ^= (row&7)
    __shared__ __align__(16) char As[TM * 256];
    __shared__ __align__(16) char Bs[TN * 256];
    __shared__ float s_fn[TM];
    __shared__ float s_cn[TN];

    const int tid  = threadIdx.x;
    const int lane = tid & 31;
    const int wid  = tid >> 5;
    const int rowBase = blockIdx.y * TM;
    const int colBase = blockIdx.x * TN;

    // ---- fill A (feat) ----
    #pragma unroll
    for (int it = 0; it < 8; it++) {
        int row = it * 16 + (tid >> 4);
        int chunk = tid & 15;
        const float4* p = (const float4*)(feat + (size_t)(rowBase + row) * FDIM + chunk * 8);
        float4 v0 = p[0], v1 = p[1];
        float s = v0.x*v0.x + v0.y*v0.y + v0.z*v0.z + v0.w*v0.w
                + v1.x*v1.x + v1.y*v1.y + v1.z*v1.z + v1.w*v1.w;
        #pragma unroll
        for (int o = 8; o; o >>= 1) s += __shfl_xor_sync(0xffffffffu, s, o);
        if (chunk == 0) s_fn[row] = s;
        uint4 w = make_uint4(pack_bf16(v0.x, v0.y), pack_bf16(v0.z, v0.w),
                             pack_bf16(v1.x, v1.y), pack_bf16(v1.z, v1.w));
        *(uint4*)(As + row * 256 + ((chunk ^ (row & 7)) << 4)) = w;
    }
    // ---- fill B (centers), zero-padded past NCLS ----
    #pragma unroll
    for (int it = 0; it < 8; it++) {
        int row = it * 16 + (tid >> 4);
        int chunk = tid & 15;
        int c = colBase + row;
        float4 v0 = make_float4(0.f,0.f,0.f,0.f), v1 = v0;
        if (c < NCLS) {
            const float4* p = (const float4*)(centers + (size_t)c * FDIM + chunk * 8);
            v0 = p[0]; v1 = p[1];
        }
        float s = v0.x*v0.x + v0.y*v0.y + v0.z*v0.z + v0.w*v0.w
                + v1.x*v1.x + v1.y*v1.y + v1.z*v1.z + v1.w*v1.w;
        #pragma unroll
        for (int o = 8; o; o >>= 1) s += __shfl_xor_sync(0xffffffffu, s, o);
        if (chunk == 0) s_cn[row] = s;
        uint4 w = make_uint4(pack_bf16(v0.x, v0.y), pack_bf16(v0.z, v0.w),
                             pack_bf16(v1.x, v1.y), pack_bf16(v1.z, v1.w));
        *(uint4*)(Bs + row * 256 + ((chunk ^ (row & 7)) << 4)) = w;
    }
    __syncthreads();

    // ---- HMMA mainloop: warp tile 64x32 (wm in {0,1}, wn in {0..3}) ----
    const int wm = wid & 1;
    const int wn = wid >> 1;
    const uint32_t aBase = smem_u32(As);
    const uint32_t bBase = smem_u32(Bs);

    float acc[4][4][4] = {};   // [mstep][nstep][d0..d3]

    #pragma unroll
    for (int ks = 0; ks < 8; ks++) {
        const int kc = ks * 2 + (lane >> 4);
        uint32_t a[4][4];
        #pragma unroll
        for (int ms = 0; ms < 4; ms++) {
            int r = wm * 64 + ms * 16 + (lane & 15);
            uint32_t addr = aBase + r * 256 + ((kc ^ (r & 7)) << 4);
            LDSM_X4(a[ms][0], a[ms][1], a[ms][2], a[ms][3], addr);
        }
        uint32_t b[4][2];
        #pragma unroll
        for (int np = 0; np < 2; np++) {
            int r = wn * 32 + np * 16 + (lane & 15);
            uint32_t addr = bBase + r * 256 + ((kc ^ (r & 7)) << 4);
            uint32_t r0, r1, r2, r3;
            LDSM_X4(r0, r1, r2, r3, addr);
            b[np*2][0] = r0; b[np*2+1][0] = r1;
            b[np*2][1] = r2; b[np*2+1][1] = r3;
        }
        #pragma unroll
        for (int ms = 0; ms < 4; ms++)
            #pragma unroll
            for (int ns = 0; ns < 4; ns++)
                MMA_BF16(acc[ms][ns], a[ms], b[ns]);
    }

    // ---- fused epilogue ----
    float* logits = out;
    float* margin = out + (size_t)BATCH * NCLS;
    float* like   = out + 2ull * BATCH * NCLS;

    const int g  = lane >> 2;    // row within 8-row group
    const int tl = lane & 3;     // col pair

    #pragma unroll
    for (int ms = 0; ms < 4; ms++) {
        #pragma unroll
        for (int half = 0; half < 2; half++) {
            int rloc = wm * 64 + ms * 16 + g + half * 8;
            int r = rowBase + rloc;
            float fn = s_fn[rloc];
            int lb = label[r];
            #pragma unroll
            for (int ns = 0; ns < 4; ns++) {
                int cloc = wn * 32 + ns * 8 + tl * 2;
                int c = colBase + cloc;
                if (c < NCLS) {   // NCLS even -> float2 all-or-nothing
                    float d0 = acc[ms][ns][half * 2];
                    float d1 = acc[ms][ns][half * 2 + 1];
                    float dist0 = fn + s_cn[cloc]     - 2.0f * d0;
                    float dist1 = fn + s_cn[cloc + 1] - 2.0f * d1;
                    float l0 = -0.5f * dist0, l1 = -0.5f * dist1;
                    bool h0 = (c == lb), h1 = (c + 1 == lb);
                    float m0 = h0 ? 2.0f * l0 : l0;
                    float m1 = h1 ? 2.0f * l1 : l1;
                    if (h0) atomicAdd(like, dist0 * (0.5f / (float)BATCH));
                    if (h1) atomicAdd(like, dist1 * (0.5f / (float)BATCH));
                    *(float2*)(logits + (size_t)r * NCLS + c) = make_float2(l0, l1);
                    *(float2*)(margin + (size_t)r * NCLS + c) = make_float2(m0, m1);
                }
            }
        }
    }
}

extern "C" void kernel_launch(void* const* d_in, const int* in_sizes, int n_in,
                              void* d_out, int out_size) {
    const float* feat    = (const float*)d_in[0];
    const int*   label   = (const int*)d_in[1];
    const float* centers = (const float*)d_in[2];
    float*       out     = (float*)d_out;

    zero_like_kernel<<<1, 1>>>(out + 2ull * BATCH * NCLS);

    dim3 grid((NCLS + TN - 1) / TN, BATCH / TM);   // 8 x 16 = 128 CTAs
    lgm_kernel<<<grid, 256>>>(feat, label, centers, out);
}